// round 14
// baseline (speedup 1.0000x reference)
#include <cuda_runtime.h>
#include <cuda_fp16.h>
#include <cstdint>

// ============================================================================
// Problem constants
// ============================================================================
#define NN    8192
#define IN_F  256
#define F     128          // OUT_F
#define MT    64           // rows per CTA (gat kernel)
#define KC    128          // j-chunk
#define NCHH  32           // chunks per CTA (j-half split)
#define NF    136          // B rows: 128 features + ones row (128) + zero pad
#define USTRD 140          // partial-u row stride (floats)

// ============================================================================
// Scratch globals (no cudaMalloc) — 16B aligned
// ============================================================================
__device__ __align__(16) float  g_s[NN];        // fp32 s
__device__ __align__(16) __half g_Y[NF * NN];   // [f][j] fp16 Wh^T (+ones row)
__device__ __align__(16) float  g_u[2 * NN * USTRD];  // per-j-half partial u

// ============================================================================
// SMEM layout (gat): single A tile + Y tile, double buffered. 102400 B/CTA
// -> 2 CTAs resident per SM (204.8 KB < 228 KB).
// ============================================================================
#define ABY   16384
#define YBY   34816
#define SAB(b) ((b) * ABY)              // 0 / 16384
#define SYB(b) (32768 + (b) * YBY)      // 32768 / 67584
#define SMEM_TOT (32768 + 2 * YBY)      // 102400

// ============================================================================
// PTX helpers (base sm_100 legal)
// ============================================================================
__device__ __forceinline__ uint32_t smem_u32(const void* p) {
    uint32_t a;
    asm("{ .reg .u64 t; cvta.to.shared.u64 t, %1; cvt.u32.u64 %0, t; }"
        : "=r"(a) : "l"(p));
    return a;
}
__device__ __forceinline__ void ldsm4(uint32_t* r, uint32_t addr) {
    asm volatile("ldmatrix.sync.aligned.m8n8.x4.shared.b16 {%0,%1,%2,%3}, [%4];"
                 : "=r"(r[0]), "=r"(r[1]), "=r"(r[2]), "=r"(r[3]) : "r"(addr));
}
__device__ __forceinline__ void ldsm2(uint32_t* r, uint32_t addr) {
    asm volatile("ldmatrix.sync.aligned.m8n8.x2.shared.b16 {%0,%1}, [%2];"
                 : "=r"(r[0]), "=r"(r[1]) : "r"(addr));
}
__device__ __forceinline__ void mma16816(float* d, const uint32_t* a,
                                         uint32_t b0, uint32_t b1) {
    asm volatile(
        "mma.sync.aligned.m16n8k16.row.col.f32.f16.f16.f32 "
        "{%0,%1,%2,%3},{%4,%5,%6,%7},{%8,%9},{%0,%1,%2,%3};"
        : "+f"(d[0]), "+f"(d[1]), "+f"(d[2]), "+f"(d[3])
        : "r"(a[0]), "r"(a[1]), "r"(a[2]), "r"(a[3]), "r"(b0), "r"(b1));
}
__device__ __forceinline__ void cpasync16(uint32_t dst, const void* src) {
    asm volatile("cp.async.cg.shared.global [%0], [%1], 16;" :: "r"(dst), "l"(src)
                 : "memory");
}
__device__ __forceinline__ void cpasync_commit() {
    asm volatile("cp.async.commit_group;" ::: "memory");
}
__device__ __forceinline__ void cpasync_wait0() {
    asm volatile("cp.async.wait_group 0;" ::: "memory");
}
__device__ __forceinline__ uint32_t h2u(__half2 v) {
    union { __half2 h; uint32_t u; } x; x.h = v; return x.u;
}
__device__ __forceinline__ float ex2f(float x) {
    float y;
    asm("ex2.approx.f32 %0, %1;" : "=f"(y) : "f"(x));
    return y;
}

// ============================================================================
// Kernel 1 (fused prep): Wh = h @ W^T ; s = Wh @ a^T (fp32) ; Y (transposed)
// (unchanged — known-good)
// ============================================================================
#define P_HS   0
#define P_WS   9216
#define P_WHS  (P_WS + 33280)
#define P_A    (P_WHS + 17024)
#define P_TOT  (P_A + 512)

__global__ __launch_bounds__(256) void prep_kernel(const float* __restrict__ h,
                                                   const float* __restrict__ W,
                                                   const float* __restrict__ a) {
    extern __shared__ char psm[];
    float* hs  = (float*)(psm + P_HS);
    float* Ws  = (float*)(psm + P_WS);
    float* whs = (float*)(psm + P_WHS);
    float* as_ = (float*)(psm + P_A);

    const int t  = threadIdx.x;
    const int i0 = blockIdx.x * 32;
    const int f  = t & 127;
    const int hf = t >> 7;

    if (t < 128) as_[t] = a[t];

    float acc[16];
#pragma unroll
    for (int i = 0; i < 16; i++) acc[i] = 0.f;

    for (int kb = 0; kb < IN_F; kb += 64) {
        __syncthreads();
        for (int idx = t; idx < 32 * 64; idx += 256) {
            int i = idx >> 6, kk = idx & 63;
            hs[kk * 36 + i] = h[(size_t)(i0 + i) * IN_F + kb + kk];
        }
        for (int idx = t; idx < 128 * 64; idx += 256) {
            int ff = idx >> 6, kk = idx & 63;
            Ws[ff * 65 + kk] = W[(size_t)ff * IN_F + kb + kk];
        }
        __syncthreads();
#pragma unroll 4
        for (int kk = 0; kk < 64; kk++) {
            float wv = Ws[f * 65 + kk];
            const float* hv = &hs[kk * 36 + hf * 16];
#pragma unroll
            for (int i = 0; i < 16; i += 4) {
                float4 v = *(const float4*)&hv[i];
                acc[i + 0] = fmaf(wv, v.x, acc[i + 0]);
                acc[i + 1] = fmaf(wv, v.y, acc[i + 1]);
                acc[i + 2] = fmaf(wv, v.z, acc[i + 2]);
                acc[i + 3] = fmaf(wv, v.w, acc[i + 3]);
            }
        }
    }
    __syncthreads();
#pragma unroll
    for (int i = 0; i < 16; i++)
        whs[(hf * 16 + i) * 133 + f] = acc[i];
    __syncthreads();

    {
        const int wid  = t >> 5;
        const int lane = t & 31;
#pragma unroll
        for (int r = 0; r < 4; r++) {
            int row = wid * 4 + r;
            float sum = 0.f;
#pragma unroll
            for (int m = 0; m < 4; m++)
                sum += whs[row * 133 + lane + 32 * m] * as_[lane + 32 * m];
#pragma unroll
            for (int off = 16; off; off >>= 1)
                sum += __shfl_xor_sync(0xffffffffu, sum, off);
            if (lane == 0) g_s[i0 + row] = sum;
        }
    }

    for (int idx = t; idx < NF * 32; idx += 256) {
        int ff = idx >> 5, i = idx & 31;
        float v = (ff < F) ? whs[i * 133 + ff] : (ff == F ? 1.0f : 0.0f);
        g_Y[(size_t)ff * NN + i0 + i] = __float2half(v);
    }
}

// ============================================================================
// Kernel 2 (main): single masked exp-GEMM, 256 threads, 2 CTAs/SM.
//   A[i,j] = adj ? 2^( lrelu(s_i+s_j)*log2(e) - 6 ) : 0
//   D = A @ B  (B = [Wh^T ; ones-row]); col 128 = denominators
// grid = 256: bid&127 -> row tile, bid>>7 -> j half.
// 8 warps: ms = wid&3 (16 rows), nh = wid>>2 (n half: 9 / 8 n-tiles)
// ============================================================================
__global__ __launch_bounds__(256, 2) void gat_kernel(const int* __restrict__ adj) {
    extern __shared__ char smem[];
    const uint32_t sb = smem_u32(smem);

    const int t    = threadIdx.x;
    const int lane = t & 31;
    const int wid  = t >> 5;
    const int ms   = wid & 3;
    const int nh   = wid >> 2;
    const int rt   = blockIdx.x & 127;
    const int jh   = blockIdx.x >> 7;
    const int i0   = rt * MT;
    const int jbase0 = jh * (NN / 2);

    const int NTN = (nh == 0) ? 9 : 8;
    float acc[9][4];
#pragma unroll
    for (int n = 0; n < 9; n++)
#pragma unroll
        for (int k = 0; k < 4; k++) acc[n][k] = 0.f;

    // ---- build-phase indices: 4 threads/row, 32 j each ----
    const int brow = t >> 2;
    const int jq   = t & 3;
    const int jb   = jq * 32;                    // first j of this thread's span
    const int ablk = jq >> 1;                    // A k-block (0/1)
    const int ainr = (jq & 1) * 64;              // byte offset in 128B row
    const uint32_t bswx = (uint32_t)((brow & 7) << 4);
    const float si = g_s[i0 + brow];

    // ---- mma-phase constants ----
    const uint32_t rA    = (uint32_t)(ms * 16 + (lane & 15));
    const uint32_t rAoff = rA * 128;
    const uint32_t swxA  = (rA & 7) << 4;
    const int khA = ((lane >> 4) & 1) * 8;
    const int khB = ((lane >> 3) & 1) * 8;
    uint32_t fOff[4], fSwx[4];
#pragma unroll
    for (int np = 0; np < 4; np++) {
        uint32_t fidx = (uint32_t)(nh * 72 + np * 16 + ((lane >> 4) & 1) * 8 + (lane & 7));
        fOff[np] = fidx * 128;
        fSwx[np] = (fidx & 7) << 4;
    }
    const uint32_t f3idx = (uint32_t)(64 + (lane & 7));   // tail tile (nh==0)
    const uint32_t f3Off = f3idx * 128;
    const uint32_t f3Swx = (f3idx & 7) << 4;

    auto stageY = [&](int jc, int bsel) {
        const uint32_t yb = sb + SYB(bsel);
        const char* ysrc = (const char*)g_Y + (size_t)jc * 2;
        for (int idx = t; idx < NF * 16; idx += 256) {
            int fr = idx >> 4, c = idx & 15;
            int blk = c >> 3, cc = c & 7;
            uint32_t dst = yb + blk * 17408 + fr * 128 + ((cc * 16) ^ ((fr & 7) << 4));
            cpasync16(dst, ysrc + (size_t)fr * (NN * 2) + c * 16);
        }
        cpasync_commit();
    };

    auto buildI = [&](const int4* av, int jc, int bsel) {
        const float4* sjp = (const float4*)(g_s + jc + jb);
        uint32_t aw[16];
#pragma unroll
        for (int p = 0; p < 8; p++) {
            int4 v = av[p];
            uint32_t m01 = __byte_perm((uint32_t)v.x, (uint32_t)v.y, 0x5410) * 0xFFFFu;
            uint32_t m23 = __byte_perm((uint32_t)v.z, (uint32_t)v.w, 0x5410) * 0xFFFFu;
            float4 sj = __ldg(&sjp[p]);
            float e0 = si + sj.x, e1 = si + sj.y, e2 = si + sj.z, e3 = si + sj.w;
            float l0 = e0 > 0.f ? e0 : 0.2f * e0;
            float l1 = e1 > 0.f ? e1 : 0.2f * e1;
            float l2 = e2 > 0.f ? e2 : 0.2f * e2;
            float l3 = e3 > 0.f ? e3 : 0.2f * e3;
            float w0 = ex2f(fmaf(l0, 1.44269504f, -6.0f));
            float w1 = ex2f(fmaf(l1, 1.44269504f, -6.0f));
            float w2 = ex2f(fmaf(l2, 1.44269504f, -6.0f));
            float w3 = ex2f(fmaf(l3, 1.44269504f, -6.0f));
            aw[2 * p]     = h2u(__floats2half2_rn(w0, w1)) & m01;
            aw[2 * p + 1] = h2u(__floats2half2_rn(w2, w3)) & m23;
        }
        char* pd = smem + SAB(bsel) + ablk * 8192 + brow * 128;
#pragma unroll
        for (int qq = 0; qq < 4; qq++) {
            uint32_t o = (uint32_t)(ainr + 16 * qq) ^ bswx;
            *(uint4*)(pd + o) = make_uint4(aw[4 * qq], aw[4 * qq + 1],
                                           aw[4 * qq + 2], aw[4 * qq + 3]);
        }
    };

    auto mmaPhase = [&](int bsel) {
        const uint32_t ab = sb + SAB(bsel) + rAoff;
        const uint32_t yb = sb + SYB(bsel);
#pragma unroll 1
        for (int ks = 0; ks < 8; ks++) {
            const int kA = ks * 16 + khA;
            const uint32_t aoff = ((uint32_t)(kA >> 6) << 13) + (((uint32_t)(kA & 63) * 2) ^ swxA);
            const int kB = ks * 16 + khB;
            const uint32_t bblk = (uint32_t)(kB >> 6) * 17408;
            const uint32_t bkin = (uint32_t)(kB & 63) * 2;
            uint32_t a[4], b[4];
            ldsm4(a, ab + aoff);
#pragma unroll
            for (int np = 0; np < 4; np++) {
                ldsm4(b, yb + bblk + fOff[np] + (bkin ^ fSwx[np]));
                mma16816(acc[2 * np],     a, b[0], b[1]);
                mma16816(acc[2 * np + 1], a, b[2], b[3]);
            }
            if (nh == 0) {
                ldsm2(b, yb + bblk + f3Off + (bkin ^ f3Swx));
                mma16816(acc[8], a, b[0], b[1]);
            }
        }
    };

    // ---- prologue: chunk 0 ----
    {
        stageY(jbase0, 0);
        int4 av[8];
        const int4* ap = (const int4*)(adj + (size_t)(i0 + brow) * NN + jbase0 + jb);
#pragma unroll
        for (int p = 0; p < 8; p++) av[p] = __ldg(&ap[p]);
        buildI(av, jbase0, 0);
        cpasync_wait0();
    }
    __syncthreads();

    // ---- pipelined main loop ----
    for (int c = 0; c < NCHH; c++) {
        const int b = c & 1;
        int4 av[8];
        const bool pf = (c + 1 < NCHH);
        const int jcn = jbase0 + (c + 1) * KC;
        if (pf) {
            const int4* ap = (const int4*)(adj + (size_t)(i0 + brow) * NN + jcn + jb);
#pragma unroll
            for (int p = 0; p < 8; p++) av[p] = __ldg(&ap[p]);
            stageY(jcn, b ^ 1);
        }
        mmaPhase(b);
        if (pf) buildI(av, jcn, b ^ 1);
        cpasync_wait0();
        __syncthreads();
    }

    // ---- write partial u (raw; softmax scale cancels globally) ----
    {
        float* up = g_u + (size_t)jh * (NN * USTRD) + (size_t)i0 * USTRD;
        const int r0 = ms * 16 + (lane >> 2);
        const int r1 = r0 + 8;
        const int cb = nh * 72 + (lane & 3) * 2;
#pragma unroll
        for (int nt = 0; nt < 9; nt++) {
            if (nt >= NTN) break;
            int col = cb + nt * 8;
            *(float2*)&up[(size_t)r0 * USTRD + col] = make_float2(acc[nt][0], acc[nt][1]);
            *(float2*)&up[(size_t)r1 * USTRD + col] = make_float2(acc[nt][2], acc[nt][3]);
        }
    }
}

// ============================================================================
// Kernel 3: combine j-half partials, normalize, LayerNorm. warp/row.
// ============================================================================
__global__ __launch_bounds__(256) void combine_kernel(const float* __restrict__ gamma,
                                                      const float* __restrict__ beta,
                                                      float* __restrict__ out) {
    const int t    = threadIdx.x;
    const int lane = t & 31;
    const int wid  = t >> 5;
    const int row  = blockIdx.x * 8 + wid;

    const float* u0 = g_u + (size_t)row * USTRD;
    const float* u1 = g_u + (size_t)NN * USTRD + (size_t)row * USTRD;

    const float inv = 1.0f / (u0[128] + u1[128]);

    const int c4 = lane * 4;
    float4 p0 = *(const float4*)&u0[c4];
    float4 p1 = *(const float4*)&u1[c4];
    float4 v;
    v.x = (p0.x + p1.x) * inv;
    v.y = (p0.y + p1.y) * inv;
    v.z = (p0.z + p1.z) * inv;
    v.w = (p0.w + p1.w) * inv;

    float sm = v.x + v.y + v.z + v.w;
    float sq = v.x * v.x + v.y * v.y + v.z * v.z + v.w * v.w;
#pragma unroll
    for (int off = 16; off; off >>= 1) {
        sm += __shfl_xor_sync(0xffffffffu, sm, off);
        sq += __shfl_xor_sync(0xffffffffu, sq, off);
    }
    const float mean = sm * (1.0f / F);
    const float var  = sq * (1.0f / F) - mean * mean;
    const float rstd = rsqrtf(var + 1e-5f);

    float4 gm = *(const float4*)&gamma[c4];
    float4 bt = *(const float4*)&beta[c4];
    float4 o;
    o.x = (v.x - mean) * rstd * gm.x + bt.x;
    o.y = (v.y - mean) * rstd * gm.y + bt.y;
    o.z = (v.z - mean) * rstd * gm.z + bt.z;
    o.w = (v.w - mean) * rstd * gm.w + bt.w;
    *(float4*)&out[(size_t)row * F + c4] = o;
}

// ============================================================================
// Launch: inputs in metadata order: h, adj, W, a, gamma, beta
// ============================================================================
extern "C" void kernel_launch(void* const* d_in, const int* in_sizes, int n_in,
                              void* d_out, int out_size) {
    const float* h     = (const float*)d_in[0];
    const int*   adj   = (const int*)  d_in[1];
    const float* W     = (const float*)d_in[2];
    const float* a     = (const float*)d_in[3];
    const float* gamma = (const float*)d_in[4];
    const float* beta  = (const float*)d_in[5];
    float* out = (float*)d_out;

    cudaFuncSetAttribute(prep_kernel, cudaFuncAttributeMaxDynamicSharedMemorySize,
                         P_TOT);
    cudaFuncSetAttribute(gat_kernel, cudaFuncAttributeMaxDynamicSharedMemorySize,
                         SMEM_TOT);

    prep_kernel<<<NN / 32, 256, P_TOT>>>(h, W, a);
    gat_kernel<<<256, 256, SMEM_TOT>>>(adj);
    combine_kernel<<<NN / 8, 256>>>(gamma, beta, out);
}

// round 15
// speedup vs baseline: 1.1386x; 1.1386x over previous
#include <cuda_runtime.h>
#include <cuda_fp16.h>
#include <cstdint>

// ============================================================================
// Problem constants
// ============================================================================
#define NN    8192
#define IN_F  256
#define F     128          // OUT_F
#define MT    64           // rows per CTA (gat kernel)
#define KC    128          // j-chunk
#define NCHH  32           // chunks per CTA (j-half split)
#define NF    136          // B rows: 128 features + ones row (128) + zero pad
#define USTRD 140          // partial-u row stride (floats)

// ============================================================================
// Scratch globals (no cudaMalloc) — 16B aligned
// ============================================================================
__device__ __align__(16) float  g_s[NN];        // fp32 s
__device__ __align__(16) __half g_Y[NF * NN];   // [f][j] fp16 Wh^T (+ones row)
__device__ __align__(16) float  g_u[2 * NN * USTRD];  // per-j-half partial u

// ============================================================================
// SMEM layout (gat): single A tile + Y tile, double buffered (R12 layout)
// ============================================================================
#define ABY   16384
#define YBY   34816
#define SAB(b) ((b) * ABY)              // 0 / 16384
#define SYB(b) (32768 + (b) * YBY)      // 32768 / 67584
#define SMEM_TOT (32768 + 2 * YBY)      // 102400

// ============================================================================
// PTX helpers (base sm_100 legal)
// ============================================================================
__device__ __forceinline__ uint32_t smem_u32(const void* p) {
    uint32_t a;
    asm("{ .reg .u64 t; cvta.to.shared.u64 t, %1; cvt.u32.u64 %0, t; }"
        : "=r"(a) : "l"(p));
    return a;
}
__device__ __forceinline__ void ldsm4(uint32_t* r, uint32_t addr) {
    asm volatile("ldmatrix.sync.aligned.m8n8.x4.shared.b16 {%0,%1,%2,%3}, [%4];"
                 : "=r"(r[0]), "=r"(r[1]), "=r"(r[2]), "=r"(r[3]) : "r"(addr));
}
__device__ __forceinline__ void ldsm2(uint32_t* r, uint32_t addr) {
    asm volatile("ldmatrix.sync.aligned.m8n8.x2.shared.b16 {%0,%1}, [%2];"
                 : "=r"(r[0]), "=r"(r[1]) : "r"(addr));
}
__device__ __forceinline__ void mma16816(float* d, const uint32_t* a,
                                         uint32_t b0, uint32_t b1) {
    asm volatile(
        "mma.sync.aligned.m16n8k16.row.col.f32.f16.f16.f32 "
        "{%0,%1,%2,%3},{%4,%5,%6,%7},{%8,%9},{%0,%1,%2,%3};"
        : "+f"(d[0]), "+f"(d[1]), "+f"(d[2]), "+f"(d[3])
        : "r"(a[0]), "r"(a[1]), "r"(a[2]), "r"(a[3]), "r"(b0), "r"(b1));
}
__device__ __forceinline__ void cpasync16(uint32_t dst, const void* src) {
    asm volatile("cp.async.cg.shared.global [%0], [%1], 16;" :: "r"(dst), "l"(src)
                 : "memory");
}
__device__ __forceinline__ void cpasync_commit() {
    asm volatile("cp.async.commit_group;" ::: "memory");
}
__device__ __forceinline__ void cpasync_wait0() {
    asm volatile("cp.async.wait_group 0;" ::: "memory");
}
__device__ __forceinline__ uint32_t h2u(__half2 v) {
    union { __half2 h; uint32_t u; } x; x.h = v; return x.u;
}
__device__ __forceinline__ float ex2f(float x) {
    float y;
    asm("ex2.approx.f32 %0, %1;" : "=f"(y) : "f"(x));
    return y;
}

// ============================================================================
// Kernel 1 (fused prep): Wh = h @ W^T ; s = Wh @ a^T (fp32) ; Y (transposed)
// 16 rows/block, grid 512, ~47.5 KB smem -> 4 CTAs/SM, single wave.
// ============================================================================
#define PT_I   16
#define P_HS   0                                  // hs  [64][20] f32 = 5120 B
#define P_WS   5120                               // Ws  [128][65] f32 = 33280 B
#define P_WHS  (P_WS + 33280)                     // whs [16][133] f32 = 8512 B
#define P_A    (P_WHS + 8512)                     // a   [128] f32
#define P_TOT  (P_A + 512)

__global__ __launch_bounds__(256) void prep_kernel(const float* __restrict__ h,
                                                   const float* __restrict__ W,
                                                   const float* __restrict__ a) {
    extern __shared__ char psm[];
    float* hs  = (float*)(psm + P_HS);    // [kk][i]  stride 20 (80 B, 16B mult)
    float* Ws  = (float*)(psm + P_WS);    // [f][kk]  stride 65
    float* whs = (float*)(psm + P_WHS);   // [i][f]   stride 133
    float* as_ = (float*)(psm + P_A);

    const int t  = threadIdx.x;
    const int i0 = blockIdx.x * PT_I;
    const int f  = t & 127;
    const int hf = t >> 7;                // 0/1 -> rows hf*8 .. +7

    if (t < 128) as_[t] = a[t];

    float acc[8];
#pragma unroll
    for (int i = 0; i < 8; i++) acc[i] = 0.f;

    for (int kb = 0; kb < IN_F; kb += 64) {
        __syncthreads();
        for (int idx = t; idx < PT_I * 64; idx += 256) {
            int i = idx >> 6, kk = idx & 63;
            hs[kk * 20 + i] = h[(size_t)(i0 + i) * IN_F + kb + kk];
        }
        for (int idx = t; idx < 128 * 64; idx += 256) {
            int ff = idx >> 6, kk = idx & 63;
            Ws[ff * 65 + kk] = W[(size_t)ff * IN_F + kb + kk];
        }
        __syncthreads();
#pragma unroll 4
        for (int kk = 0; kk < 64; kk++) {
            float wv = Ws[f * 65 + kk];
            const float* hv = &hs[kk * 20 + hf * 8];
#pragma unroll
            for (int i = 0; i < 8; i += 4) {
                float4 v = *(const float4*)&hv[i];
                acc[i + 0] = fmaf(wv, v.x, acc[i + 0]);
                acc[i + 1] = fmaf(wv, v.y, acc[i + 1]);
                acc[i + 2] = fmaf(wv, v.z, acc[i + 2]);
                acc[i + 3] = fmaf(wv, v.w, acc[i + 3]);
            }
        }
    }
    __syncthreads();
#pragma unroll
    for (int i = 0; i < 8; i++)
        whs[(hf * 8 + i) * 133 + f] = acc[i];
    __syncthreads();

    // s per row: warp w -> rows 2w..2w+1
    {
        const int wid  = t >> 5;
        const int lane = t & 31;
#pragma unroll
        for (int r = 0; r < 2; r++) {
            int row = wid * 2 + r;
            float sum = 0.f;
#pragma unroll
            for (int m = 0; m < 4; m++)
                sum += whs[row * 133 + lane + 32 * m] * as_[lane + 32 * m];
#pragma unroll
            for (int off = 16; off; off >>= 1)
                sum += __shfl_xor_sync(0xffffffffu, sum, off);
            if (lane == 0) g_s[i0 + row] = sum;
        }
    }

    // Y tile: g_Y[f][i0+i], ones row at f=128, zero pad above
    for (int idx = t; idx < NF * PT_I; idx += 256) {
        int ff = idx >> 4, i = idx & (PT_I - 1);
        float v = (ff < F) ? whs[i * 133 + ff] : (ff == F ? 1.0f : 0.0f);
        g_Y[(size_t)ff * NN + i0 + i] = __float2half(v);
    }
}

// ============================================================================
// Kernel 2 (main): single masked exp-GEMM — EXACT R12 configuration (best).
//   A[i,j] = adj ? 2^( lrelu(s_i+s_j)*log2(e) - 6 ) : 0
//   D = A @ B  (B = [Wh^T ; ones-row]); col 128 = denominators
// grid = 256: bid&127 -> row tile, bid>>7 -> j half. 512 threads.
// ============================================================================
__global__ __launch_bounds__(512, 1) void gat_kernel(const int* __restrict__ adj) {
    extern __shared__ char smem[];
    const uint32_t sb = smem_u32(smem);

    const int t    = threadIdx.x;
    const int lane = t & 31;
    const int wid  = t >> 5;
    const int ms   = wid & 3;     // m slice (16 rows)
    const int nq   = wid >> 2;    // n quarter
    const int rt   = blockIdx.x & 127;
    const int jh   = blockIdx.x >> 7;
    const int i0   = rt * MT;
    const int jbase0 = jh * (NN / 2);

    const int NT = (nq == 3) ? 5 : 4;
    float acc[5][4];
#pragma unroll
    for (int n = 0; n < 5; n++)
#pragma unroll
        for (int k = 0; k < 4; k++) acc[n][k] = 0.f;

    // ---- build-phase indices: 8 threads/row, 16 j each ----
    const int brow = t >> 3;
    const int jq   = t & 7;
    const int jb8  = jq * 16;
    const int jbyte0 = jb8 * 2;
    const uint32_t bldoff = (uint32_t)(((jbyte0 >> 7) << 13) + brow * 128);
    const uint32_t bswx   = (uint32_t)((brow & 7) << 4);
    const uint32_t binner = (uint32_t)(jbyte0 & 127);
    const float si = g_s[i0 + brow];

    // ---- mma-phase constants ----
    const uint32_t rA    = (uint32_t)(ms * 16 + (lane & 15));
    const uint32_t rAoff = rA * 128;
    const uint32_t swxA  = (rA & 7) << 4;
    const int khA = ((lane >> 4) & 1) * 8;
    const int khB = ((lane >> 3) & 1) * 8;
    uint32_t fOff[2], fSwx[2];
#pragma unroll
    for (int np = 0; np < 2; np++) {
        uint32_t fidx = (uint32_t)(nq * 32 + np * 16 + ((lane >> 4) & 1) * 8 + (lane & 7));
        fOff[np] = fidx * 128;
        fSwx[np] = (fidx & 7) << 4;
    }
    const uint32_t f3idx = (uint32_t)(128 + (lane & 7));
    const uint32_t f3Off = f3idx * 128;
    const uint32_t f3Swx = (f3idx & 7) << 4;

    auto stageY = [&](int jc, int bsel) {
        const uint32_t yb = sb + SYB(bsel);
        const char* ysrc = (const char*)g_Y + (size_t)jc * 2;
        for (int idx = t; idx < NF * 16; idx += 512) {
            int fr = idx >> 4, c = idx & 15;
            int blk = c >> 3, cc = c & 7;
            uint32_t dst = yb + blk * 17408 + fr * 128 + ((cc * 16) ^ ((fr & 7) << 4));
            cpasync16(dst, ysrc + (size_t)fr * (NN * 2) + c * 16);
        }
        cpasync_commit();
    };

    auto buildI = [&](const int4* av, int jc, int bsel) {
        const float4* sjp = (const float4*)(g_s + jc + jb8);
        uint32_t aw[8];
#pragma unroll
        for (int p = 0; p < 4; p++) {
            int4 v = av[p];
            uint32_t m01 = __byte_perm((uint32_t)v.x, (uint32_t)v.y, 0x5410) * 0xFFFFu;
            uint32_t m23 = __byte_perm((uint32_t)v.z, (uint32_t)v.w, 0x5410) * 0xFFFFu;
            float4 sj = __ldg(&sjp[p]);
            float e0 = si + sj.x, e1 = si + sj.y, e2 = si + sj.z, e3 = si + sj.w;
            float l0 = e0 > 0.f ? e0 : 0.2f * e0;
            float l1 = e1 > 0.f ? e1 : 0.2f * e1;
            float l2 = e2 > 0.f ? e2 : 0.2f * e2;
            float l3 = e3 > 0.f ? e3 : 0.2f * e3;
            float w0 = ex2f(fmaf(l0, 1.44269504f, -6.0f));
            float w1 = ex2f(fmaf(l1, 1.44269504f, -6.0f));
            float w2 = ex2f(fmaf(l2, 1.44269504f, -6.0f));
            float w3 = ex2f(fmaf(l3, 1.44269504f, -6.0f));
            aw[2 * p]     = h2u(__floats2half2_rn(w0, w1)) & m01;
            aw[2 * p + 1] = h2u(__floats2half2_rn(w2, w3)) & m23;
        }
        char* pd = smem + SAB(bsel) + bldoff;
#pragma unroll
        for (int qq = 0; qq < 2; qq++) {
            uint32_t o = (binner + 16 * qq) ^ bswx;
            *(uint4*)(pd + o) = make_uint4(aw[4 * qq], aw[4 * qq + 1],
                                           aw[4 * qq + 2], aw[4 * qq + 3]);
        }
    };

    auto mmaPhase = [&](int bsel) {
        const uint32_t ab = sb + SAB(bsel) + rAoff;
        const uint32_t yb = sb + SYB(bsel);
#pragma unroll 1
        for (int ks = 0; ks < 8; ks++) {
            const int kA = ks * 16 + khA;
            const uint32_t aoff = ((uint32_t)(kA >> 6) << 13) + (((uint32_t)(kA & 63) * 2) ^ swxA);
            const int kB = ks * 16 + khB;
            const uint32_t bblk = (uint32_t)(kB >> 6) * 17408;
            const uint32_t bkin = (uint32_t)(kB & 63) * 2;
            uint32_t a[4], b[4];
            ldsm4(a, ab + aoff);
#pragma unroll
            for (int np = 0; np < 2; np++) {
                ldsm4(b, yb + bblk + fOff[np] + (bkin ^ fSwx[np]));
                mma16816(acc[2 * np],     a, b[0], b[1]);
                mma16816(acc[2 * np + 1], a, b[2], b[3]);
            }
            if (nq == 3) {
                ldsm2(b, yb + bblk + f3Off + (bkin ^ f3Swx));
                mma16816(acc[4], a, b[0], b[1]);
            }
        }
    };

    // ---- prologue: chunk 0 ----
    {
        stageY(jbase0, 0);
        int4 av[4];
        const int4* ap = (const int4*)(adj + (size_t)(i0 + brow) * NN + jbase0 + jb8);
#pragma unroll
        for (int p = 0; p < 4; p++) av[p] = __ldg(&ap[p]);
        buildI(av, jbase0, 0);
        cpasync_wait0();
    }
    __syncthreads();

    // ---- pipelined main loop ----
    for (int c = 0; c < NCHH; c++) {
        const int b = c & 1;
        int4 av[4];
        const bool pf = (c + 1 < NCHH);
        const int jcn = jbase0 + (c + 1) * KC;
        if (pf) {
            const int4* ap = (const int4*)(adj + (size_t)(i0 + brow) * NN + jcn + jb8);
#pragma unroll
            for (int p = 0; p < 4; p++) av[p] = __ldg(&ap[p]);
            stageY(jcn, b ^ 1);
        }
        mmaPhase(b);
        if (pf) buildI(av, jcn, b ^ 1);
        cpasync_wait0();
        __syncthreads();
    }

    // ---- write partial u (raw; softmax scale cancels globally) ----
    {
        float* up = g_u + (size_t)jh * (NN * USTRD) + (size_t)i0 * USTRD;
        const int r0 = ms * 16 + (lane >> 2);
        const int r1 = r0 + 8;
        const int cb = nq * 32 + (lane & 3) * 2;
#pragma unroll
        for (int nt = 0; nt < 5; nt++) {
            if (nt >= NT) break;
            int col = cb + nt * 8;
            *(float2*)&up[(size_t)r0 * USTRD + col] = make_float2(acc[nt][0], acc[nt][1]);
            *(float2*)&up[(size_t)r1 * USTRD + col] = make_float2(acc[nt][2], acc[nt][3]);
        }
    }
}

// ============================================================================
// Kernel 3: combine j-half partials, normalize, LayerNorm. warp/row.
// ============================================================================
__global__ __launch_bounds__(256) void combine_kernel(const float* __restrict__ gamma,
                                                      const float* __restrict__ beta,
                                                      float* __restrict__ out) {
    const int t    = threadIdx.x;
    const int lane = t & 31;
    const int wid  = t >> 5;
    const int row  = blockIdx.x * 8 + wid;

    const float* u0 = g_u + (size_t)row * USTRD;
    const float* u1 = g_u + (size_t)NN * USTRD + (size_t)row * USTRD;

    const float inv = 1.0f / (u0[128] + u1[128]);

    const int c4 = lane * 4;
    float4 p0 = *(const float4*)&u0[c4];
    float4 p1 = *(const float4*)&u1[c4];
    float4 v;
    v.x = (p0.x + p1.x) * inv;
    v.y = (p0.y + p1.y) * inv;
    v.z = (p0.z + p1.z) * inv;
    v.w = (p0.w + p1.w) * inv;

    float sm = v.x + v.y + v.z + v.w;
    float sq = v.x * v.x + v.y * v.y + v.z * v.z + v.w * v.w;
#pragma unroll
    for (int off = 16; off; off >>= 1) {
        sm += __shfl_xor_sync(0xffffffffu, sm, off);
        sq += __shfl_xor_sync(0xffffffffu, sq, off);
    }
    const float mean = sm * (1.0f / F);
    const float var  = sq * (1.0f / F) - mean * mean;
    const float rstd = rsqrtf(var + 1e-5f);

    float4 gm = *(const float4*)&gamma[c4];
    float4 bt = *(const float4*)&beta[c4];
    float4 o;
    o.x = (v.x - mean) * rstd * gm.x + bt.x;
    o.y = (v.y - mean) * rstd * gm.y + bt.y;
    o.z = (v.z - mean) * rstd * gm.z + bt.z;
    o.w = (v.w - mean) * rstd * gm.w + bt.w;
    *(float4*)&out[(size_t)row * F + c4] = o;
}

// ============================================================================
// Launch: inputs in metadata order: h, adj, W, a, gamma, beta
// ============================================================================
extern "C" void kernel_launch(void* const* d_in, const int* in_sizes, int n_in,
                              void* d_out, int out_size) {
    const float* h     = (const float*)d_in[0];
    const int*   adj   = (const int*)  d_in[1];
    const float* W     = (const float*)d_in[2];
    const float* a     = (const float*)d_in[3];
    const float* gamma = (const float*)d_in[4];
    const float* beta  = (const float*)d_in[5];
    float* out = (float*)d_out;

    cudaFuncSetAttribute(prep_kernel, cudaFuncAttributeMaxDynamicSharedMemorySize,
                         P_TOT);
    cudaFuncSetAttribute(gat_kernel, cudaFuncAttributeMaxDynamicSharedMemorySize,
                         SMEM_TOT);

    prep_kernel<<<NN / PT_I, 256, P_TOT>>>(h, W, a);
    gat_kernel<<<256, 512, SMEM_TOT>>>(adj);
    combine_kernel<<<NN / 8, 256>>>(gamma, beta, out);
}

// round 16
// speedup vs baseline: 1.2067x; 1.0598x over previous
#include <cuda_runtime.h>
#include <cuda_fp16.h>
#include <cstdint>

// ============================================================================
// Problem constants
// ============================================================================
#define NN    8192
#define IN_F  256
#define F     128          // OUT_F
#define MT    64           // rows per CTA (gat kernel)
#define KC    128          // j-chunk
#define NCHH  32           // chunks per CTA (j-half split)
#define NF    136          // B rows: 128 features + ones row (128) + zero pad
#define USTRD 140          // partial-u row stride (floats)

// ============================================================================
// Scratch globals (no cudaMalloc) — 16B aligned
// ============================================================================
__device__ __align__(16) float  g_s[NN];        // fp32 s
__device__ __align__(16) __half g_Y[NF * NN];   // [f][j] fp16 Wh^T (+ones row)
__device__ __align__(16) float  g_u[2 * NN * USTRD];  // per-j-half partial u

// ============================================================================
// SMEM layout (gat): single A tile + Y tile, double buffered (R12 layout)
// ============================================================================
#define ABY   16384
#define YBY   34816
#define SAB(b) ((b) * ABY)              // 0 / 16384
#define SYB(b) (32768 + (b) * YBY)      // 32768 / 67584
#define SMEM_TOT (32768 + 2 * YBY)      // 102400

// ============================================================================
// PTX helpers (base sm_100 legal)
// ============================================================================
__device__ __forceinline__ uint32_t smem_u32(const void* p) {
    uint32_t a;
    asm("{ .reg .u64 t; cvta.to.shared.u64 t, %1; cvt.u32.u64 %0, t; }"
        : "=r"(a) : "l"(p));
    return a;
}
__device__ __forceinline__ void ldsm4(uint32_t* r, uint32_t addr) {
    asm volatile("ldmatrix.sync.aligned.m8n8.x4.shared.b16 {%0,%1,%2,%3}, [%4];"
                 : "=r"(r[0]), "=r"(r[1]), "=r"(r[2]), "=r"(r[3]) : "r"(addr));
}
__device__ __forceinline__ void ldsm2(uint32_t* r, uint32_t addr) {
    asm volatile("ldmatrix.sync.aligned.m8n8.x2.shared.b16 {%0,%1}, [%2];"
                 : "=r"(r[0]), "=r"(r[1]) : "r"(addr));
}
__device__ __forceinline__ void mma16816(float* d, const uint32_t* a,
                                         uint32_t b0, uint32_t b1) {
    asm volatile(
        "mma.sync.aligned.m16n8k16.row.col.f32.f16.f16.f32 "
        "{%0,%1,%2,%3},{%4,%5,%6,%7},{%8,%9},{%0,%1,%2,%3};"
        : "+f"(d[0]), "+f"(d[1]), "+f"(d[2]), "+f"(d[3])
        : "r"(a[0]), "r"(a[1]), "r"(a[2]), "r"(a[3]), "r"(b0), "r"(b1));
}
__device__ __forceinline__ void cpasync16(uint32_t dst, const void* src) {
    asm volatile("cp.async.cg.shared.global [%0], [%1], 16;" :: "r"(dst), "l"(src)
                 : "memory");
}
__device__ __forceinline__ void cpasync_commit() {
    asm volatile("cp.async.commit_group;" ::: "memory");
}
__device__ __forceinline__ void cpasync_wait0() {
    asm volatile("cp.async.wait_group 0;" ::: "memory");
}
__device__ __forceinline__ uint32_t h2u(__half2 v) {
    union { __half2 h; uint32_t u; } x; x.h = v; return x.u;
}
__device__ __forceinline__ float ex2f(float x) {
    float y;
    asm("ex2.approx.f32 %0, %1;" : "=f"(y) : "f"(x));
    return y;
}

// ============================================================================
// Kernel 1 (fused prep): Wh = h @ W^T ; s = Wh @ a^T (fp32) ; Y (transposed)
// 32 rows/CTA (grid 256 — W staged once per 32 rows), 512 threads (16 warps)
// to halve the per-thread staging + FMA critical path.
// ============================================================================
#define P_HS   0                                  // hs  [64][36] f32 = 9216 B
#define P_WS   9216                               // Ws  [128][65] f32 = 33280 B
#define P_WHS  (P_WS + 33280)                     // whs [32][133] f32 = 17024 B
#define P_A    (P_WHS + 17024)                    // a   [128] f32
#define P_TOT  (P_A + 512)

__global__ __launch_bounds__(512) void prep_kernel(const float* __restrict__ h,
                                                   const float* __restrict__ W,
                                                   const float* __restrict__ a) {
    extern __shared__ char psm[];
    float* hs  = (float*)(psm + P_HS);    // [kk][i]  stride 36 (144 B, 16B mult)
    float* Ws  = (float*)(psm + P_WS);    // [f][kk]  stride 65
    float* whs = (float*)(psm + P_WHS);   // [i][f]   stride 133
    float* as_ = (float*)(psm + P_A);

    const int t  = threadIdx.x;
    const int i0 = blockIdx.x * 32;
    const int f  = t & 127;
    const int hf = t >> 7;                // 0..3 -> rows hf*8 .. +7

    if (t < 128) as_[t] = a[t];

    float acc[8];
#pragma unroll
    for (int i = 0; i < 8; i++) acc[i] = 0.f;

    for (int kb = 0; kb < IN_F; kb += 64) {
        __syncthreads();
        for (int idx = t; idx < 32 * 64; idx += 512) {
            int i = idx >> 6, kk = idx & 63;
            hs[kk * 36 + i] = h[(size_t)(i0 + i) * IN_F + kb + kk];
        }
        for (int idx = t; idx < 128 * 64; idx += 512) {
            int ff = idx >> 6, kk = idx & 63;
            Ws[ff * 65 + kk] = W[(size_t)ff * IN_F + kb + kk];
        }
        __syncthreads();
#pragma unroll 4
        for (int kk = 0; kk < 64; kk++) {
            float wv = Ws[f * 65 + kk];
            const float* hv = &hs[kk * 36 + hf * 8];
#pragma unroll
            for (int i = 0; i < 8; i += 4) {
                float4 v = *(const float4*)&hv[i];
                acc[i + 0] = fmaf(wv, v.x, acc[i + 0]);
                acc[i + 1] = fmaf(wv, v.y, acc[i + 1]);
                acc[i + 2] = fmaf(wv, v.z, acc[i + 2]);
                acc[i + 3] = fmaf(wv, v.w, acc[i + 3]);
            }
        }
    }
    __syncthreads();
#pragma unroll
    for (int i = 0; i < 8; i++)
        whs[(hf * 8 + i) * 133 + f] = acc[i];
    __syncthreads();

    // s per row: warp w (0..15) -> rows 2w..2w+1
    {
        const int wid  = t >> 5;
        const int lane = t & 31;
#pragma unroll
        for (int r = 0; r < 2; r++) {
            int row = wid * 2 + r;
            float sum = 0.f;
#pragma unroll
            for (int m = 0; m < 4; m++)
                sum += whs[row * 133 + lane + 32 * m] * as_[lane + 32 * m];
#pragma unroll
            for (int off = 16; off; off >>= 1)
                sum += __shfl_xor_sync(0xffffffffu, sum, off);
            if (lane == 0) g_s[i0 + row] = sum;
        }
    }

    // Y tile: g_Y[f][i0+i], ones row at f=128, zero pad above
    for (int idx = t; idx < NF * 32; idx += 512) {
        int ff = idx >> 5, i = idx & 31;
        float v = (ff < F) ? whs[i * 133 + ff] : (ff == F ? 1.0f : 0.0f);
        g_Y[(size_t)ff * NN + i0 + i] = __float2half(v);
    }
}

// ============================================================================
// Kernel 2 (main): single masked exp-GEMM — EXACT R12 configuration (best).
//   A[i,j] = adj ? 2^( lrelu(s_i+s_j)*log2(e) - 6 ) : 0
//   D = A @ B  (B = [Wh^T ; ones-row]); col 128 = denominators
// grid = 256: bid&127 -> row tile, bid>>7 -> j half. 512 threads.
// ============================================================================
__global__ __launch_bounds__(512, 1) void gat_kernel(const int* __restrict__ adj) {
    extern __shared__ char smem[];
    const uint32_t sb = smem_u32(smem);

    const int t    = threadIdx.x;
    const int lane = t & 31;
    const int wid  = t >> 5;
    const int ms   = wid & 3;     // m slice (16 rows)
    const int nq   = wid >> 2;    // n quarter
    const int rt   = blockIdx.x & 127;
    const int jh   = blockIdx.x >> 7;
    const int i0   = rt * MT;
    const int jbase0 = jh * (NN / 2);

    const int NT = (nq == 3) ? 5 : 4;
    float acc[5][4];
#pragma unroll
    for (int n = 0; n < 5; n++)
#pragma unroll
        for (int k = 0; k < 4; k++) acc[n][k] = 0.f;

    // ---- build-phase indices: 8 threads/row, 16 j each ----
    const int brow = t >> 3;
    const int jq   = t & 7;
    const int jb8  = jq * 16;
    const int jbyte0 = jb8 * 2;
    const uint32_t bldoff = (uint32_t)(((jbyte0 >> 7) << 13) + brow * 128);
    const uint32_t bswx   = (uint32_t)((brow & 7) << 4);
    const uint32_t binner = (uint32_t)(jbyte0 & 127);
    const float si = g_s[i0 + brow];

    // ---- mma-phase constants ----
    const uint32_t rA    = (uint32_t)(ms * 16 + (lane & 15));
    const uint32_t rAoff = rA * 128;
    const uint32_t swxA  = (rA & 7) << 4;
    const int khA = ((lane >> 4) & 1) * 8;
    const int khB = ((lane >> 3) & 1) * 8;
    uint32_t fOff[2], fSwx[2];
#pragma unroll
    for (int np = 0; np < 2; np++) {
        uint32_t fidx = (uint32_t)(nq * 32 + np * 16 + ((lane >> 4) & 1) * 8 + (lane & 7));
        fOff[np] = fidx * 128;
        fSwx[np] = (fidx & 7) << 4;
    }
    const uint32_t f3idx = (uint32_t)(128 + (lane & 7));
    const uint32_t f3Off = f3idx * 128;
    const uint32_t f3Swx = (f3idx & 7) << 4;

    auto stageY = [&](int jc, int bsel) {
        const uint32_t yb = sb + SYB(bsel);
        const char* ysrc = (const char*)g_Y + (size_t)jc * 2;
        for (int idx = t; idx < NF * 16; idx += 512) {
            int fr = idx >> 4, c = idx & 15;
            int blk = c >> 3, cc = c & 7;
            uint32_t dst = yb + blk * 17408 + fr * 128 + ((cc * 16) ^ ((fr & 7) << 4));
            cpasync16(dst, ysrc + (size_t)fr * (NN * 2) + c * 16);
        }
        cpasync_commit();
    };

    auto buildI = [&](const int4* av, int jc, int bsel) {
        const float4* sjp = (const float4*)(g_s + jc + jb8);
        uint32_t aw[8];
#pragma unroll
        for (int p = 0; p < 4; p++) {
            int4 v = av[p];
            uint32_t m01 = __byte_perm((uint32_t)v.x, (uint32_t)v.y, 0x5410) * 0xFFFFu;
            uint32_t m23 = __byte_perm((uint32_t)v.z, (uint32_t)v.w, 0x5410) * 0xFFFFu;
            float4 sj = __ldg(&sjp[p]);
            float e0 = si + sj.x, e1 = si + sj.y, e2 = si + sj.z, e3 = si + sj.w;
            float l0 = e0 > 0.f ? e0 : 0.2f * e0;
            float l1 = e1 > 0.f ? e1 : 0.2f * e1;
            float l2 = e2 > 0.f ? e2 : 0.2f * e2;
            float l3 = e3 > 0.f ? e3 : 0.2f * e3;
            float w0 = ex2f(fmaf(l0, 1.44269504f, -6.0f));
            float w1 = ex2f(fmaf(l1, 1.44269504f, -6.0f));
            float w2 = ex2f(fmaf(l2, 1.44269504f, -6.0f));
            float w3 = ex2f(fmaf(l3, 1.44269504f, -6.0f));
            aw[2 * p]     = h2u(__floats2half2_rn(w0, w1)) & m01;
            aw[2 * p + 1] = h2u(__floats2half2_rn(w2, w3)) & m23;
        }
        char* pd = smem + SAB(bsel) + bldoff;
#pragma unroll
        for (int qq = 0; qq < 2; qq++) {
            uint32_t o = (binner + 16 * qq) ^ bswx;
            *(uint4*)(pd + o) = make_uint4(aw[4 * qq], aw[4 * qq + 1],
                                           aw[4 * qq + 2], aw[4 * qq + 3]);
        }
    };

    auto mmaPhase = [&](int bsel) {
        const uint32_t ab = sb + SAB(bsel) + rAoff;
        const uint32_t yb = sb + SYB(bsel);
#pragma unroll 1
        for (int ks = 0; ks < 8; ks++) {
            const int kA = ks * 16 + khA;
            const uint32_t aoff = ((uint32_t)(kA >> 6) << 13) + (((uint32_t)(kA & 63) * 2) ^ swxA);
            const int kB = ks * 16 + khB;
            const uint32_t bblk = (uint32_t)(kB >> 6) * 17408;
            const uint32_t bkin = (uint32_t)(kB & 63) * 2;
            uint32_t a[4], b[4];
            ldsm4(a, ab + aoff);
#pragma unroll
            for (int np = 0; np < 2; np++) {
                ldsm4(b, yb + bblk + fOff[np] + (bkin ^ fSwx[np]));
                mma16816(acc[2 * np],     a, b[0], b[1]);
                mma16816(acc[2 * np + 1], a, b[2], b[3]);
            }
            if (nq == 3) {
                ldsm2(b, yb + bblk + f3Off + (bkin ^ f3Swx));
                mma16816(acc[4], a, b[0], b[1]);
            }
        }
    };

    // ---- prologue: chunk 0 ----
    {
        stageY(jbase0, 0);
        int4 av[4];
        const int4* ap = (const int4*)(adj + (size_t)(i0 + brow) * NN + jbase0 + jb8);
#pragma unroll
        for (int p = 0; p < 4; p++) av[p] = __ldg(&ap[p]);
        buildI(av, jbase0, 0);
        cpasync_wait0();
    }
    __syncthreads();

    // ---- pipelined main loop ----
    for (int c = 0; c < NCHH; c++) {
        const int b = c & 1;
        int4 av[4];
        const bool pf = (c + 1 < NCHH);
        const int jcn = jbase0 + (c + 1) * KC;
        if (pf) {
            const int4* ap = (const int4*)(adj + (size_t)(i0 + brow) * NN + jcn + jb8);
#pragma unroll
            for (int p = 0; p < 4; p++) av[p] = __ldg(&ap[p]);
            stageY(jcn, b ^ 1);
        }
        mmaPhase(b);
        if (pf) buildI(av, jcn, b ^ 1);
        cpasync_wait0();
        __syncthreads();
    }

    // ---- write partial u (raw; softmax scale cancels globally) ----
    {
        float* up = g_u + (size_t)jh * (NN * USTRD) + (size_t)i0 * USTRD;
        const int r0 = ms * 16 + (lane >> 2);
        const int r1 = r0 + 8;
        const int cb = nq * 32 + (lane & 3) * 2;
#pragma unroll
        for (int nt = 0; nt < 5; nt++) {
            if (nt >= NT) break;
            int col = cb + nt * 8;
            *(float2*)&up[(size_t)r0 * USTRD + col] = make_float2(acc[nt][0], acc[nt][1]);
            *(float2*)&up[(size_t)r1 * USTRD + col] = make_float2(acc[nt][2], acc[nt][3]);
        }
    }
}

// ============================================================================
// Kernel 3: combine j-half partials, normalize, LayerNorm. warp/row.
// ============================================================================
__global__ __launch_bounds__(256) void combine_kernel(const float* __restrict__ gamma,
                                                      const float* __restrict__ beta,
                                                      float* __restrict__ out) {
    const int t    = threadIdx.x;
    const int lane = t & 31;
    const int wid  = t >> 5;
    const int row  = blockIdx.x * 8 + wid;

    const float* u0 = g_u + (size_t)row * USTRD;
    const float* u1 = g_u + (size_t)NN * USTRD + (size_t)row * USTRD;

    const float inv = 1.0f / (u0[128] + u1[128]);

    const int c4 = lane * 4;
    float4 p0 = *(const float4*)&u0[c4];
    float4 p1 = *(const float4*)&u1[c4];
    float4 v;
    v.x = (p0.x + p1.x) * inv;
    v.y = (p0.y + p1.y) * inv;
    v.z = (p0.z + p1.z) * inv;
    v.w = (p0.w + p1.w) * inv;

    float sm = v.x + v.y + v.z + v.w;
    float sq = v.x * v.x + v.y * v.y + v.z * v.z + v.w * v.w;
#pragma unroll
    for (int off = 16; off; off >>= 1) {
        sm += __shfl_xor_sync(0xffffffffu, sm, off);
        sq += __shfl_xor_sync(0xffffffffu, sq, off);
    }
    const float mean = sm * (1.0f / F);
    const float var  = sq * (1.0f / F) - mean * mean;
    const float rstd = rsqrtf(var + 1e-5f);

    float4 gm = *(const float4*)&gamma[c4];
    float4 bt = *(const float4*)&beta[c4];
    float4 o;
    o.x = (v.x - mean) * rstd * gm.x + bt.x;
    o.y = (v.y - mean) * rstd * gm.y + bt.y;
    o.z = (v.z - mean) * rstd * gm.z + bt.z;
    o.w = (v.w - mean) * rstd * gm.w + bt.w;
    *(float4*)&out[(size_t)row * F + c4] = o;
}

// ============================================================================
// Launch: inputs in metadata order: h, adj, W, a, gamma, beta
// ============================================================================
extern "C" void kernel_launch(void* const* d_in, const int* in_sizes, int n_in,
                              void* d_out, int out_size) {
    const float* h     = (const float*)d_in[0];
    const int*   adj   = (const int*)  d_in[1];
    const float* W     = (const float*)d_in[2];
    const float* a     = (const float*)d_in[3];
    const float* gamma = (const float*)d_in[4];
    const float* beta  = (const float*)d_in[5];
    float* out = (float*)d_out;

    cudaFuncSetAttribute(prep_kernel, cudaFuncAttributeMaxDynamicSharedMemorySize,
                         P_TOT);
    cudaFuncSetAttribute(gat_kernel, cudaFuncAttributeMaxDynamicSharedMemorySize,
                         SMEM_TOT);

    prep_kernel<<<NN / 32, 512, P_TOT>>>(h, W, a);
    gat_kernel<<<256, 512, SMEM_TOT>>>(adj);
    combine_kernel<<<NN / 8, 256>>>(gamma, beta, out);
}

// round 17
// speedup vs baseline: 1.2109x; 1.0035x over previous
#include <cuda_runtime.h>
#include <cuda_fp16.h>
#include <cstdint>

// ============================================================================
// Problem constants
// ============================================================================
#define NN    8192
#define IN_F  256
#define F     128          // OUT_F
#define MT    64           // rows per CTA (gat kernel)
#define KC    128          // j-chunk
#define NCHH  32           // chunks per CTA (j-half split)
#define NF    136          // B rows: 128 features + ones row (128) + zero pad
#define USTRD 140          // partial-u row stride (floats)

// ============================================================================
// Scratch globals (no cudaMalloc) — 16B aligned
// ============================================================================
__device__ __align__(16) float  g_s[NN];        // fp32 s
__device__ __align__(16) __half g_Y[NF * NN];   // [f][j] fp16 Wh^T (+ones row)
__device__ __align__(16) float  g_u[2 * NN * USTRD];  // per-j-half partial u

// ============================================================================
// SMEM layout (gat): single A tile + Y tile, double buffered (R12 layout)
// ============================================================================
#define ABY   16384
#define YBY   34816
#define SAB(b) ((b) * ABY)              // 0 / 16384
#define SYB(b) (32768 + (b) * YBY)      // 32768 / 67584
#define SMEM_TOT (32768 + 2 * YBY)      // 102400

// ============================================================================
// PTX helpers (base sm_100 legal)
// ============================================================================
__device__ __forceinline__ uint32_t smem_u32(const void* p) {
    uint32_t a;
    asm("{ .reg .u64 t; cvta.to.shared.u64 t, %1; cvt.u32.u64 %0, t; }"
        : "=r"(a) : "l"(p));
    return a;
}
__device__ __forceinline__ void ldsm4(uint32_t* r, uint32_t addr) {
    asm volatile("ldmatrix.sync.aligned.m8n8.x4.shared.b16 {%0,%1,%2,%3}, [%4];"
                 : "=r"(r[0]), "=r"(r[1]), "=r"(r[2]), "=r"(r[3]) : "r"(addr));
}
__device__ __forceinline__ void ldsm2(uint32_t* r, uint32_t addr) {
    asm volatile("ldmatrix.sync.aligned.m8n8.x2.shared.b16 {%0,%1}, [%2];"
                 : "=r"(r[0]), "=r"(r[1]) : "r"(addr));
}
__device__ __forceinline__ void mma16816(float* d, const uint32_t* a,
                                         uint32_t b0, uint32_t b1) {
    asm volatile(
        "mma.sync.aligned.m16n8k16.row.col.f32.f16.f16.f32 "
        "{%0,%1,%2,%3},{%4,%5,%6,%7},{%8,%9},{%0,%1,%2,%3};"
        : "+f"(d[0]), "+f"(d[1]), "+f"(d[2]), "+f"(d[3])
        : "r"(a[0]), "r"(a[1]), "r"(a[2]), "r"(a[3]), "r"(b0), "r"(b1));
}
__device__ __forceinline__ void cpasync16(uint32_t dst, const void* src) {
    asm volatile("cp.async.cg.shared.global [%0], [%1], 16;" :: "r"(dst), "l"(src)
                 : "memory");
}
__device__ __forceinline__ void cpasync_commit() {
    asm volatile("cp.async.commit_group;" ::: "memory");
}
__device__ __forceinline__ void cpasync_wait0() {
    asm volatile("cp.async.wait_group 0;" ::: "memory");
}
__device__ __forceinline__ uint32_t h2u(__half2 v) {
    union { __half2 h; uint32_t u; } x; x.h = v; return x.u;
}
__device__ __forceinline__ float ex2f(float x) {
    float y;
    asm("ex2.approx.f32 %0, %1;" : "=f"(y) : "f"(x));
    return y;
}

// ============================================================================
// Kernel 1 (fused prep) — R16 version (41-42 us; known-sticky, leave alone)
// ============================================================================
#define P_HS   0                                  // hs  [64][36] f32
#define P_WS   9216                               // Ws  [128][65] f32
#define P_WHS  (P_WS + 33280)                     // whs [32][133] f32
#define P_A    (P_WHS + 17024)
#define P_TOT  (P_A + 512)

__global__ __launch_bounds__(512) void prep_kernel(const float* __restrict__ h,
                                                   const float* __restrict__ W,
                                                   const float* __restrict__ a) {
    extern __shared__ char psm[];
    float* hs  = (float*)(psm + P_HS);
    float* Ws  = (float*)(psm + P_WS);
    float* whs = (float*)(psm + P_WHS);
    float* as_ = (float*)(psm + P_A);

    const int t  = threadIdx.x;
    const int i0 = blockIdx.x * 32;
    const int f  = t & 127;
    const int hf = t >> 7;

    if (t < 128) as_[t] = a[t];

    float acc[8];
#pragma unroll
    for (int i = 0; i < 8; i++) acc[i] = 0.f;

    for (int kb = 0; kb < IN_F; kb += 64) {
        __syncthreads();
        for (int idx = t; idx < 32 * 64; idx += 512) {
            int i = idx >> 6, kk = idx & 63;
            hs[kk * 36 + i] = h[(size_t)(i0 + i) * IN_F + kb + kk];
        }
        for (int idx = t; idx < 128 * 64; idx += 512) {
            int ff = idx >> 6, kk = idx & 63;
            Ws[ff * 65 + kk] = W[(size_t)ff * IN_F + kb + kk];
        }
        __syncthreads();
#pragma unroll 4
        for (int kk = 0; kk < 64; kk++) {
            float wv = Ws[f * 65 + kk];
            const float* hv = &hs[kk * 36 + hf * 8];
#pragma unroll
            for (int i = 0; i < 8; i += 4) {
                float4 v = *(const float4*)&hv[i];
                acc[i + 0] = fmaf(wv, v.x, acc[i + 0]);
                acc[i + 1] = fmaf(wv, v.y, acc[i + 1]);
                acc[i + 2] = fmaf(wv, v.z, acc[i + 2]);
                acc[i + 3] = fmaf(wv, v.w, acc[i + 3]);
            }
        }
    }
    __syncthreads();
#pragma unroll
    for (int i = 0; i < 8; i++)
        whs[(hf * 8 + i) * 133 + f] = acc[i];
    __syncthreads();

    {
        const int wid  = t >> 5;
        const int lane = t & 31;
#pragma unroll
        for (int r = 0; r < 2; r++) {
            int row = wid * 2 + r;
            float sum = 0.f;
#pragma unroll
            for (int m = 0; m < 4; m++)
                sum += whs[row * 133 + lane + 32 * m] * as_[lane + 32 * m];
#pragma unroll
            for (int off = 16; off; off >>= 1)
                sum += __shfl_xor_sync(0xffffffffu, sum, off);
            if (lane == 0) g_s[i0 + row] = sum;
        }
    }

    for (int idx = t; idx < NF * 32; idx += 512) {
        int ff = idx >> 5, i = idx & 31;
        float v = (ff < F) ? whs[i * 133 + ff] : (ff == F ? 1.0f : 0.0f);
        g_Y[(size_t)ff * NN + i0 + i] = __float2half(v);
    }
}

// ============================================================================
// Kernel 2 (main): single masked exp-GEMM; warp grid rebalanced to
//   2 m-slices (32 rows, 2 A frags) x 8 n-tiles (16 cols) per warp
// to cut B ldsm redundancy 4x -> 1x (A redundancy 4x -> 8x, but A is 4.5x
// smaller). Total smem wavefronts/chunk ~2880 -> ~1570.
// grid = 256: bid&127 -> row tile, bid>>7 -> j half. 512 threads.
// ============================================================================
__global__ __launch_bounds__(512, 1) void gat_kernel(const int* __restrict__ adj) {
    extern __shared__ char smem[];
    const uint32_t sb = smem_u32(smem);

    const int t    = threadIdx.x;
    const int lane = t & 31;
    const int wid  = t >> 5;
    const int ms   = wid & 1;     // m slice (32 rows)
    const int nq   = wid >> 1;    // n 16-col tile (0..7)
    const int rt   = blockIdx.x & 127;
    const int jh   = blockIdx.x >> 7;
    const int i0   = rt * MT;
    const int jbase0 = jh * (NN / 2);

    // acc tiles: [mf*2+nf] main (mf in 0..1 rows +0/+16, nf in 0..1 cols +0/+8)
    // + tail tiles 4,5 (col 128 block) for nq==7
    const bool hasTail = (nq == 7);
    float acc[6][4];
#pragma unroll
    for (int n = 0; n < 6; n++)
#pragma unroll
        for (int k = 0; k < 4; k++) acc[n][k] = 0.f;

    // ---- build-phase indices: 8 threads/row, 16 j each (unchanged) ----
    const int brow = t >> 3;
    const int jq   = t & 7;
    const int jb8  = jq * 16;
    const int jbyte0 = jb8 * 2;
    const uint32_t bldoff = (uint32_t)(((jbyte0 >> 7) << 13) + brow * 128);
    const uint32_t bswx   = (uint32_t)((brow & 7) << 4);
    const uint32_t binner = (uint32_t)(jbyte0 & 127);
    const float si = g_s[i0 + brow];

    // ---- mma-phase constants ----
    const uint32_t rA0    = (uint32_t)(ms * 32 + (lane & 15));
    const uint32_t rAoff0 = rA0 * 128;              // A fragment 0 rows
    const uint32_t rAoff1 = rAoff0 + 16 * 128;      // A fragment 1 rows (+16)
    const uint32_t swxA   = (rA0 & 7) << 4;         // (rA0+16)&7 == rA0&7
    const int khA = ((lane >> 4) & 1) * 8;
    const int khB = ((lane >> 3) & 1) * 8;
    const uint32_t fidx = (uint32_t)(nq * 16 + ((lane >> 4) & 1) * 8 + (lane & 7));
    const uint32_t fOff = fidx * 128;
    const uint32_t fSwx = (fidx & 7) << 4;
    const uint32_t f3idx = (uint32_t)(128 + (lane & 7));
    const uint32_t f3Off = f3idx * 128;
    const uint32_t f3Swx = (f3idx & 7) << 4;

    auto stageY = [&](int jc, int bsel) {
        const uint32_t yb = sb + SYB(bsel);
        const char* ysrc = (const char*)g_Y + (size_t)jc * 2;
        for (int idx = t; idx < NF * 16; idx += 512) {
            int fr = idx >> 4, c = idx & 15;
            int blk = c >> 3, cc = c & 7;
            uint32_t dst = yb + blk * 17408 + fr * 128 + ((cc * 16) ^ ((fr & 7) << 4));
            cpasync16(dst, ysrc + (size_t)fr * (NN * 2) + c * 16);
        }
        cpasync_commit();
    };

    auto buildI = [&](const int4* av, int jc, int bsel) {
        const float4* sjp = (const float4*)(g_s + jc + jb8);
        uint32_t aw[8];
#pragma unroll
        for (int p = 0; p < 4; p++) {
            int4 v = av[p];
            uint32_t m01 = __byte_perm((uint32_t)v.x, (uint32_t)v.y, 0x5410) * 0xFFFFu;
            uint32_t m23 = __byte_perm((uint32_t)v.z, (uint32_t)v.w, 0x5410) * 0xFFFFu;
            float4 sj = __ldg(&sjp[p]);
            float e0 = si + sj.x, e1 = si + sj.y, e2 = si + sj.z, e3 = si + sj.w;
            float l0 = e0 > 0.f ? e0 : 0.2f * e0;
            float l1 = e1 > 0.f ? e1 : 0.2f * e1;
            float l2 = e2 > 0.f ? e2 : 0.2f * e2;
            float l3 = e3 > 0.f ? e3 : 0.2f * e3;
            float w0 = ex2f(fmaf(l0, 1.44269504f, -6.0f));
            float w1 = ex2f(fmaf(l1, 1.44269504f, -6.0f));
            float w2 = ex2f(fmaf(l2, 1.44269504f, -6.0f));
            float w3 = ex2f(fmaf(l3, 1.44269504f, -6.0f));
            aw[2 * p]     = h2u(__floats2half2_rn(w0, w1)) & m01;
            aw[2 * p + 1] = h2u(__floats2half2_rn(w2, w3)) & m23;
        }
        char* pd = smem + SAB(bsel) + bldoff;
#pragma unroll
        for (int qq = 0; qq < 2; qq++) {
            uint32_t o = (binner + 16 * qq) ^ bswx;
            *(uint4*)(pd + o) = make_uint4(aw[4 * qq], aw[4 * qq + 1],
                                           aw[4 * qq + 2], aw[4 * qq + 3]);
        }
    };

    auto mmaPhase = [&](int bsel) {
        const uint32_t ab = sb + SAB(bsel);
        const uint32_t yb = sb + SYB(bsel);
#pragma unroll 1
        for (int ks = 0; ks < 8; ks++) {
            const int kA = ks * 16 + khA;
            const uint32_t aoff = ((uint32_t)(kA >> 6) << 13) +
                                  (((uint32_t)(kA & 63) * 2) ^ swxA);
            const int kB = ks * 16 + khB;
            const uint32_t bblk = (uint32_t)(kB >> 6) * 17408;
            const uint32_t bkin = (uint32_t)(kB & 63) * 2;
            uint32_t a0[4], a1[4], b[4];
            ldsm4(a0, ab + rAoff0 + aoff);
            ldsm4(a1, ab + rAoff1 + aoff);
            ldsm4(b, yb + bblk + fOff + (bkin ^ fSwx));
            mma16816(acc[0], a0, b[0], b[1]);   // mf0, nf0
            mma16816(acc[1], a0, b[2], b[3]);   // mf0, nf1
            mma16816(acc[2], a1, b[0], b[1]);   // mf1, nf0
            mma16816(acc[3], a1, b[2], b[3]);   // mf1, nf1
            if (hasTail) {
                ldsm2(b, yb + bblk + f3Off + (bkin ^ f3Swx));
                mma16816(acc[4], a0, b[0], b[1]);
                mma16816(acc[5], a1, b[0], b[1]);
            }
        }
    };

    // ---- prologue: chunk 0 ----
    {
        stageY(jbase0, 0);
        int4 av[4];
        const int4* ap = (const int4*)(adj + (size_t)(i0 + brow) * NN + jbase0 + jb8);
#pragma unroll
        for (int p = 0; p < 4; p++) av[p] = __ldg(&ap[p]);
        buildI(av, jbase0, 0);
        cpasync_wait0();
    }
    __syncthreads();

    // ---- pipelined main loop ----
    for (int c = 0; c < NCHH; c++) {
        const int b = c & 1;
        int4 av[4];
        const bool pf = (c + 1 < NCHH);
        const int jcn = jbase0 + (c + 1) * KC;
        if (pf) {
            const int4* ap = (const int4*)(adj + (size_t)(i0 + brow) * NN + jcn + jb8);
#pragma unroll
            for (int p = 0; p < 4; p++) av[p] = __ldg(&ap[p]);
            stageY(jcn, b ^ 1);
        }
        mmaPhase(b);
        if (pf) buildI(av, jcn, b ^ 1);
        cpasync_wait0();
        __syncthreads();
    }

    // ---- write partial u (raw; softmax scale cancels globally) ----
    {
        float* up = g_u + (size_t)jh * (NN * USTRD) + (size_t)i0 * USTRD;
        const int cb = nq * 16 + (lane & 3) * 2;
#pragma unroll
        for (int mf = 0; mf < 2; mf++) {
            const int r0 = ms * 32 + mf * 16 + (lane >> 2);
            const int r1 = r0 + 8;
#pragma unroll
            for (int nf = 0; nf < 2; nf++) {
                const float* d = acc[mf * 2 + nf];
                int col = cb + nf * 8;
                *(float2*)&up[(size_t)r0 * USTRD + col] = make_float2(d[0], d[1]);
                *(float2*)&up[(size_t)r1 * USTRD + col] = make_float2(d[2], d[3]);
            }
            if (hasTail) {
                const float* d = acc[4 + mf];
                int col = 128 + (lane & 3) * 2;
                *(float2*)&up[(size_t)r0 * USTRD + col] = make_float2(d[0], d[1]);
                *(float2*)&up[(size_t)r1 * USTRD + col] = make_float2(d[2], d[3]);
            }
        }
    }
}

// ============================================================================
// Kernel 3: combine j-half partials, normalize, LayerNorm. warp/row.
// ============================================================================
__global__ __launch_bounds__(256) void combine_kernel(const float* __restrict__ gamma,
                                                      const float* __restrict__ beta,
                                                      float* __restrict__ out) {
    const int t    = threadIdx.x;
    const int lane = t & 31;
    const int wid  = t >> 5;
    const int row  = blockIdx.x * 8 + wid;

    const float* u0 = g_u + (size_t)row * USTRD;
    const float* u1 = g_u + (size_t)NN * USTRD + (size_t)row * USTRD;

    const float inv = 1.0f / (u0[128] + u1[128]);

    const int c4 = lane * 4;
    float4 p0 = *(const float4*)&u0[c4];
    float4 p1 = *(const float4*)&u1[c4];
    float4 v;
    v.x = (p0.x + p1.x) * inv;
    v.y = (p0.y + p1.y) * inv;
    v.z = (p0.z + p1.z) * inv;
    v.w = (p0.w + p1.w) * inv;

    float sm = v.x + v.y + v.z + v.w;
    float sq = v.x * v.x + v.y * v.y + v.z * v.z + v.w * v.w;
#pragma unroll
    for (int off = 16; off; off >>= 1) {
        sm += __shfl_xor_sync(0xffffffffu, sm, off);
        sq += __shfl_xor_sync(0xffffffffu, sq, off);
    }
    const float mean = sm * (1.0f / F);
    const float var  = sq * (1.0f / F) - mean * mean;
    const float rstd = rsqrtf(var + 1e-5f);

    float4 gm = *(const float4*)&gamma[c4];
    float4 bt = *(const float4*)&beta[c4];
    float4 o;
    o.x = (v.x - mean) * rstd * gm.x + bt.x;
    o.y = (v.y - mean) * rstd * gm.y + bt.y;
    o.z = (v.z - mean) * rstd * gm.z + bt.z;
    o.w = (v.w - mean) * rstd * gm.w + bt.w;
    *(float4*)&out[(size_t)row * F + c4] = o;
}

// ============================================================================
// Launch: inputs in metadata order: h, adj, W, a, gamma, beta
// ============================================================================
extern "C" void kernel_launch(void* const* d_in, const int* in_sizes, int n_in,
                              void* d_out, int out_size) {
    const float* h     = (const float*)d_in[0];
    const int*   adj   = (const int*)  d_in[1];
    const float* W     = (const float*)d_in[2];
    const float* a     = (const float*)d_in[3];
    const float* gamma = (const float*)d_in[4];
    const float* beta  = (const float*)d_in[5];
    float* out = (float*)d_out;

    cudaFuncSetAttribute(prep_kernel, cudaFuncAttributeMaxDynamicSharedMemorySize,
                         P_TOT);
    cudaFuncSetAttribute(gat_kernel, cudaFuncAttributeMaxDynamicSharedMemorySize,
                         SMEM_TOT);

    prep_kernel<<<NN / 32, 512, P_TOT>>>(h, W, a);
    gat_kernel<<<256, 512, SMEM_TOT>>>(adj);
    combine_kernel<<<NN / 8, 256>>>(gamma, beta, out);
}